// round 9
// baseline (speedup 1.0000x reference)
#include <cuda_runtime.h>
#include <cuda_bf16.h>
#include <cstdint>

typedef unsigned int u32;
typedef unsigned long long u64;

#define SIGMA_C 162.13039087945623f
#define MU_C    117.41975505778706f

// ---- smem byte offsets ----
#define P_OFF     0        /* 448 rows x 20 floats = 35840 B (overlaid by W tables at init) */
#define W0P_OFF   0
#define W1P_OFF   7680
#define W2P_OFF   12288
#define XB_OFF    35840    /* 4 buffers x (64 rows x 112 B) = 28672 */
#define XBUF(k)   (XB_OFF + (k) * 7168)
#define CS_OFF    64512    /* 448 f32 */
#define BIAS0_OFF 66304
#define BIAS1_OFF 66496
#define BIAS2_OFF 66592
#define FCW_OFF   66688    /* 686 f32 */
#define RED_OFF   69440    /* 4 f32 */
#define SMEM_BYTES 69504

static __device__ __forceinline__ u32 smem_u32(const void* p) {
    u32 a;
    asm("{ .reg .u64 t; cvta.to.shared.u64 t, %1; cvt.u32.u64 %0, t; }" : "=r"(a) : "l"(p));
    return a;
}
static __device__ __forceinline__ float fast_tanh(float x) {
    float y; asm("tanh.approx.f32 %0, %1;" : "=f"(y) : "f"(x)); return y;
}
#define CVT2(res, lo, hi) \
    asm("cvt.rn.bf16x2.f32 %0, %1, %2;" : "=r"(res) : "f"(hi), "f"(lo))

static __device__ __forceinline__ void mma16816(float* d, const u32* a, const u32* b) {
    asm volatile("mma.sync.aligned.m16n8k16.row.col.f32.bf16.bf16.f32 "
        "{%0,%1,%2,%3}, {%4,%5,%6,%7}, {%8,%9}, {%0,%1,%2,%3};"
        : "+f"(d[0]), "+f"(d[1]), "+f"(d[2]), "+f"(d[3])
        : "r"(a[0]), "r"(a[1]), "r"(a[2]), "r"(a[3]), "r"(b[0]), "r"(b[1]));
}
static __device__ __forceinline__ void ldm4(u32* r, u32 addr) {
    asm volatile("ldmatrix.sync.aligned.m8n8.x4.shared.b16 {%0,%1,%2,%3}, [%4];"
        : "=r"(r[0]), "=r"(r[1]), "=r"(r[2]), "=r"(r[3]) : "r"(addr));
}
static __device__ __forceinline__ u64 pk2(float x) {
    u64 r; asm("mov.b64 %0, {%1, %1};" : "=l"(r) : "f"(x)); return r;
}
static __device__ __forceinline__ void upk(u64 v, float& a, float& b) {
    asm("mov.b64 {%0, %1}, %2;" : "=f"(a), "=f"(b) : "l"(v));
}
static __device__ __forceinline__ u64 ffma2(u64 a, u64 b, u64 c) {
    u64 d; asm("fma.rn.f32x2 %0, %1, %2, %3;" : "=l"(d) : "l"(a), "l"(b), "l"(c)); return d;
}

__global__ void __launch_bounds__(32) init_out_kernel(float* out, int B) {
    int i = threadIdx.x;
    if (i < B) out[i] = MU_C;
}

__global__ void __launch_bounds__(128, 2) gnn_mma_kernel(
    const float* __restrict__ feat,
    const float* __restrict__ nbc,
    const float* __restrict__ wts,
    const float* __restrict__ wscal,
    const float* __restrict__ w0, const float* __restrict__ b0,
    const float* __restrict__ w1, const float* __restrict__ b1,
    const float* __restrict__ w2, const float* __restrict__ b2,
    const float* __restrict__ w3, const float* __restrict__ b3,
    const float* __restrict__ w4, const float* __restrict__ b4,
    const float* __restrict__ wf, const float* __restrict__ bff,
    float* __restrict__ out, int N, int B)
{
    extern __shared__ char smem[];
    float* smf = (float*)smem;
    const int tid  = threadIdx.x;
    const int warp = tid >> 5;
    const int lane = tid & 31;
    const int n0 = blockIdx.x * 64;
    const int nvalid = (N - n0 < 64) ? (N - n0) : 64;
    const int vrows = nvalid * 7;
    const u32 sb = smem_u32(smem);

    // ---- one-time init ----
    {
        float* w0p = smf + W0P_OFF / 4;
        for (int i = tid; i < 40 * 48; i += 128) { int n = i / 48, k = i % 48; w0p[i] = (k < 40) ? w0[n * 40 + k] : 0.f; }
        float* w1p = smf + W1P_OFF / 4;
        for (int i = tid; i < 24 * 48; i += 128) { int n = i / 48, k = i % 48; w1p[i] = (n < 20 && k < 40) ? w1[n * 40 + k] : 0.f; }
        float* w2p = smf + W2P_OFF / 4;
        for (int i = tid; i < 24 * 32; i += 128) { int n = i / 32, k = i % 32; w2p[i] = (n < 20 && k < 20) ? w2[n * 20 + k] : 0.f; }
        float* bb0 = smf + BIAS0_OFF / 4;
        for (int i = tid; i < 48; i += 128) bb0[i] = (i < 40) ? b0[i] : 0.f;
        float* bb1 = smf + BIAS1_OFF / 4;
        for (int i = tid; i < 24; i += 128) bb1[i] = (i < 20) ? b1[i] : 0.f;
        float* bb2 = smf + BIAS2_OFF / 4;
        for (int i = tid; i < 24; i += 128) bb2[i] = (i < 20) ? b2[i] : 0.f;
        float* fw = smf + FCW_OFF / 4;
        for (int i = tid; i < 400; i += 128) { int j = i / 20, k = i % 20; fw[k * 20 + j] = w3[i]; }
        for (int i = tid; i < 20;  i += 128) fw[400 + i] = b3[i];
        for (int i = tid; i < 240; i += 128) { int k = i / 12, j = i % 12; fw[420 + i] = (j < 10) ? w4[j * 20 + k] : 0.f; }
        for (int i = tid; i < 12;  i += 128) fw[660 + i] = (i < 10) ? b4[i] : 0.f;
        for (int i = tid; i < 12;  i += 128) fw[672 + i] = (i < 10) ? wf[i] : 0.f;
        if (tid == 0) { fw[684] = wscal[0]; fw[685] = bff[0]; }

        if (tid < 64) {
            float cs[7] = {0.f, 0.f, 0.f, 0.f, 0.f, 0.f, 0.f};
            int node = n0 + tid;
            if (node < N) {
                float c0a = nbc[node * 6 + 0], c0b = nbc[node * 6 + 1], c0c = nbc[node * 6 + 2];
                float c1a = nbc[node * 6 + 3], c1b = nbc[node * 6 + 4], c1c = nbc[node * 6 + 5];
                float w_ = wscal[0];
                float nb0 = c0a + c0b + c0c, nb1 = c1a + c1b + c1c;
                float nb0s = (nb0 < 1e-5f) ? 1e-5f : nb0;
                float nb1s = (nb1 < 1e-5f) ? 1e-5f : nb1;
                float h0 = (nb0 > 0.f) ? 1.f : 0.f;
                float h1 = (nb1 > 0.f) ? 1.f : 0.f;
                float inv0 = w_ / nb0s, inv1 = w_ / nb1s;
                cs[0] = 1.f - h0 * w_ - h1 * w_;
                cs[1] = c0a * inv0; cs[2] = c0b * inv0; cs[3] = c0c * inv0;
                cs[4] = c1a * inv1; cs[5] = c1b * inv1; cs[6] = c1c * inv1;
            }
            #pragma unroll
            for (int s = 0; s < 7; s++) smf[CS_OFF / 4 + tid * 7 + s] = cs[s];
        }

        // zero k-pad columns (bytes 80..111) of all 4 X buffers
        for (int i = tid; i < 256; i += 128) {
            int buf = i >> 6, row = i & 63;
            u32* pz = (u32*)(smem + XBUF(buf) + row * 112 + 80);
            #pragma unroll
            for (int c = 0; c < 8; c++) pz[c] = 0u;
        }
    }
    __syncthreads();

    // ---- persistent B fragments ----
    const int q = lane & 3;
    const int nn = lane >> 2;
    u32 w0f[15][2], w1f[9][2], w2f[6][2];
    {
        const float* w0p = smf + W0P_OFF / 4;
        #pragma unroll
        for (int f = 0; f < 3; f++)
            #pragma unroll
            for (int j = 0; j < 5; j++) {
                int k0 = f * 16 + 2 * q;
                const float* r = &w0p[(j * 8 + nn) * 48];
                CVT2(w0f[f * 5 + j][0], r[k0 + 0], r[k0 + 1]);
                CVT2(w0f[f * 5 + j][1], r[k0 + 8], r[k0 + 9]);
            }
        const float* w1p = smf + W1P_OFF / 4;
        #pragma unroll
        for (int f = 0; f < 3; f++)
            #pragma unroll
            for (int j = 0; j < 3; j++) {
                int k0 = f * 16 + 2 * q;
                const float* r = &w1p[(j * 8 + nn) * 48];
                CVT2(w1f[f * 3 + j][0], r[k0 + 0], r[k0 + 1]);
                CVT2(w1f[f * 3 + j][1], r[k0 + 8], r[k0 + 9]);
            }
        const float* w2p = smf + W2P_OFF / 4;
        #pragma unroll
        for (int f = 0; f < 2; f++)
            #pragma unroll
            for (int j = 0; j < 3; j++) {
                int k0 = f * 16 + 2 * q;
                const float* r = &w2p[(j * 8 + nn) * 32];
                CVT2(w2f[f * 3 + j][0], r[k0 + 0], r[k0 + 1]);
                CVT2(w2f[f * 3 + j][1], r[k0 + 8], r[k0 + 9]);
            }
    }

    const float* bb0 = smf + BIAS0_OFF / 4;
    const float* bb1 = smf + BIAS1_OFF / 4;
    const float* bb2 = smf + BIAS2_OFF / 4;
    const float* csa = smf + CS_OFF / 4;
    const float* fw  = smf + FCW_OFF / 4;

    int srow[5], soff[5], goff[5];
    #pragma unroll
    for (int it = 0; it < 5; it++) {
        int i = it * 128 + tid;
        int row = i / 10, qq = i % 10;
        srow[it] = row;
        soff[it] = row * 112 + qq * 8;
        goff[it] = row * 10 + qq;
    }

    const int lg = lane >> 3, lr = lane & 7;
    const int arow = warp * 16 + (lg & 1) * 8 + lr;
    const int acolb = (lg >> 1) * 8;
    const int prow = warp * 16 + (lane >> 2);

    const float wt = (tid < nvalid) ? wts[n0 + tid] : 0.f;

    // One fc0 chain for 16 rows starting at global tile row base `rbase`,
    // reading X from `xbase`. Emits epilogue3 into P.
    #define CHAIN_L0(AF, XB_)                                                   \
        u32 AF[3][4];                                                           \
        { _Pragma("unroll")                                                     \
          for (int f = 0; f < 3; f++)                                           \
              ldm4(AF[f], (XB_) + (u32)(arow * 112 + (f * 16 + acolb) * 2)); }

    #define CHAIN_MMA0(D, AF)                                                   \
        float D[5][4];                                                          \
        { _Pragma("unroll")                                                     \
          for (int j = 0; j < 5; j++) { D[j][0]=0.f; D[j][1]=0.f; D[j][2]=0.f; D[j][3]=0.f; } \
          _Pragma("unroll")                                                     \
          for (int f = 0; f < 3; f++)                                           \
              { _Pragma("unroll")                                               \
                for (int j = 0; j < 5; j++) mma16816(D[j], AF[f], w0f[f * 5 + j]); } }

    #define CHAIN_EPI1(A1, D)                                                   \
        u32 A1[3][4];                                                           \
        { _Pragma("unroll")                                                     \
          for (int j = 0; j < 5; j++) {                                         \
              int c0 = j * 8 + 2 * q;                                           \
              float bl = bb0[c0], bh = bb0[c0 + 1];                             \
              float t0 = fast_tanh(D[j][0] + bl);                               \
              float t1 = fast_tanh(D[j][1] + bh);                               \
              float t2 = fast_tanh(D[j][2] + bl);                               \
              float t3 = fast_tanh(D[j][3] + bh);                               \
              u32 plo, phi; CVT2(plo, t0, t1); CVT2(phi, t2, t3);               \
              A1[j >> 1][(j & 1) ? 2 : 0] = plo;                                \
              A1[j >> 1][(j & 1) ? 3 : 1] = phi;                                \
          }                                                                     \
          A1[2][2] = 0u; A1[2][3] = 0u; }

    #define CHAIN_MMA1(E, A1)                                                   \
        float E[3][4];                                                          \
        { _Pragma("unroll")                                                     \
          for (int j = 0; j < 3; j++) { E[j][0]=0.f; E[j][1]=0.f; E[j][2]=0.f; E[j][3]=0.f; } \
          _Pragma("unroll")                                                     \
          for (int f = 0; f < 3; f++)                                           \
              { _Pragma("unroll")                                               \
                for (int j = 0; j < 3; j++) mma16816(E[j], A1[f], w1f[f * 3 + j]); } }

    #define CHAIN_EPI2(A2, E)                                                   \
        u32 A2[2][4];                                                           \
        { _Pragma("unroll")                                                     \
          for (int j = 0; j < 3; j++) {                                         \
              int c0 = j * 8 + 2 * q;                                           \
              float bl = bb1[c0], bh = bb1[c0 + 1];                             \
              float t0 = (c0 < 20)     ? fast_tanh(E[j][0] + bl) : 0.f;         \
              float t1 = (c0 + 1 < 20) ? fast_tanh(E[j][1] + bh) : 0.f;         \
              float t2 = (c0 < 20)     ? fast_tanh(E[j][2] + bl) : 0.f;         \
              float t3 = (c0 + 1 < 20) ? fast_tanh(E[j][3] + bh) : 0.f;         \
              u32 plo, phi; CVT2(plo, t0, t1); CVT2(phi, t2, t3);               \
              A2[j >> 1][(j & 1) ? 2 : 0] = plo;                                \
              A2[j >> 1][(j & 1) ? 3 : 1] = phi;                                \
          }                                                                     \
          A2[1][2] = 0u; A2[1][3] = 0u; }

    #define CHAIN_MMA2(O, A2)                                                   \
        float O[3][4];                                                          \
        { _Pragma("unroll")                                                     \
          for (int j = 0; j < 3; j++) { O[j][0]=0.f; O[j][1]=0.f; O[j][2]=0.f; O[j][3]=0.f; } \
          _Pragma("unroll")                                                     \
          for (int f = 0; f < 2; f++)                                           \
              { _Pragma("unroll")                                               \
                for (int j = 0; j < 3; j++) mma16816(O[j], A2[f], w2f[f * 3 + j]); } }

    #define CHAIN_EPI3(O, TT)                                                   \
        { int r0 = (TT) * 64 + prow;                                            \
          int r1 = r0 + 8;                                                      \
          float cs0 = csa[r0], cs1 = csa[r1];                                   \
          _Pragma("unroll")                                                     \
          for (int j = 0; j < 3; j++) {                                         \
              int c0 = j * 8 + 2 * q;                                           \
              if (c0 < 20) {                                                    \
                  float bl = bb2[c0], bh = bb2[c0 + 1];                         \
                  float v0 = cs0 * fast_tanh(O[j][0] + bl);                     \
                  float v1 = cs0 * fast_tanh(O[j][1] + bh);                     \
                  float v2 = cs1 * fast_tanh(O[j][2] + bl);                     \
                  float v3 = cs1 * fast_tanh(O[j][3] + bh);                     \
                  *(float2*)(smem + P_OFF + (u32)(r0 * 80 + c0 * 4)) = make_float2(v0, v1); \
                  *(float2*)(smem + P_OFF + (u32)(r1 * 80 + c0 * 4)) = make_float2(v2, v3); \
              } } }

    float4 xv[10];   // staged quads: [0..4] tile A, [5..9] tile B

    #pragma unroll 1
    for (int bq = 0; bq < B; bq++) {
        const float4* fbB = (const float4*)feat + ((size_t)bq * N + n0) * 70;

        if (bq == 0) {
            #pragma unroll
            for (int it = 0; it < 5; it++) {
                if (srow[it] < vrows)        xv[it]     = fbB[goff[it]];
                if (64 + srow[it] < vrows)   xv[5 + it] = fbB[640 + goff[it]];
            }
        }

        #pragma unroll 1
        for (int pt = 0; pt < 3; pt++) {
            const int tA = 2 * pt, tB = 2 * pt + 1;
            const u32 xbA = sb + XBUF((pt & 1) << 1);
            const u32 xbB = sb + XBUF(((pt & 1) << 1) + 1);

            // STS both tiles
            #pragma unroll
            for (int it = 0; it < 5; it++) {
                u32 p0, p1;
                CVT2(p0, xv[it].x, xv[it].y);
                CVT2(p1, xv[it].z, xv[it].w);
                asm volatile("st.shared.v2.b32 [%0], {%1, %2};"
                             :: "r"(xbA + (u32)soff[it]), "r"(p0), "r"(p1) : "memory");
                CVT2(p0, xv[5 + it].x, xv[5 + it].y);
                CVT2(p1, xv[5 + it].z, xv[5 + it].w);
                asm volatile("st.shared.v2.b32 [%0], {%1, %2};"
                             :: "r"(xbB + (u32)soff[it]), "r"(p0), "r"(p1) : "memory");
            }
            __syncthreads();

            // prefetch next tiles under compute
            if (pt < 2) {
                #pragma unroll
                for (int it = 0; it < 5; it++) {
                    if ((tA + 2) * 64 + srow[it] < vrows) xv[it]     = fbB[(tA + 2) * 640 + goff[it]];
                    if ((tB + 2) * 64 + srow[it] < vrows) xv[5 + it] = fbB[(tB + 2) * 640 + goff[it]];
                }
            } else {
                #pragma unroll
                for (int it = 0; it < 5; it++)
                    if (6 * 64 + srow[it] < vrows) xv[it] = fbB[6 * 640 + goff[it]];
            }

            // interleaved dual chains
            CHAIN_L0(a0fA, xbA)
            CHAIN_L0(a0fB, xbB)
            CHAIN_MMA0(dA, a0fA)
            CHAIN_MMA0(dB, a0fB)
            CHAIN_EPI1(a1fA, dA)
            CHAIN_EPI1(a1fB, dB)
            CHAIN_MMA1(eA, a1fA)
            CHAIN_MMA1(eB, a1fB)
            CHAIN_EPI2(a2fA, eA)
            CHAIN_EPI2(a2fB, eB)
            CHAIN_MMA2(oA, a2fA)
            CHAIN_MMA2(oB, a2fB)
            CHAIN_EPI3(oA, tA)
            CHAIN_EPI3(oB, tB)
        }

        // tile 6 (single chain)
        {
            const u32 xb6 = sb + XBUF(2);
            #pragma unroll
            for (int it = 0; it < 5; it++) {
                u32 p0, p1;
                CVT2(p0, xv[it].x, xv[it].y);
                CVT2(p1, xv[it].z, xv[it].w);
                asm volatile("st.shared.v2.b32 [%0], {%1, %2};"
                             :: "r"(xb6 + (u32)soff[it]), "r"(p0), "r"(p1) : "memory");
            }
            __syncthreads();

            // prefetch next batch's first pair under compute
            if (bq + 1 < B) {
                const float4* fbN = (const float4*)feat + ((size_t)(bq + 1) * N + n0) * 70;
                #pragma unroll
                for (int it = 0; it < 5; it++) {
                    if (srow[it] < vrows)      xv[it]     = fbN[goff[it]];
                    if (64 + srow[it] < vrows) xv[5 + it] = fbN[640 + goff[it]];
                }
            }

            CHAIN_L0(a0fA, xb6)
            CHAIN_MMA0(dA, a0fA)
            CHAIN_EPI1(a1fA, dA)
            CHAIN_MMA1(eA, a1fA)
            CHAIN_EPI2(a2fA, eA)
            CHAIN_MMA2(oA, a2fA)
            CHAIN_EPI3(oA, 6)
        }
        __syncthreads();   // P complete

        // ---- tail: gather P, fc1, head ----
        float contrib = 0.f;
        if (tid < nvalid) {
            float m[20];
            #pragma unroll
            for (int d2 = 0; d2 < 20; d2++) m[d2] = 0.f;
            #pragma unroll
            for (int s = 0; s < 7; s++) {
                const float4* pr = (const float4*)(smem + P_OFF + (u32)((tid * 7 + s) * 80));
                #pragma unroll
                for (int c = 0; c < 5; c++) {
                    float4 vv = pr[c];
                    m[4 * c + 0] += vv.x; m[4 * c + 1] += vv.y;
                    m[4 * c + 2] += vv.z; m[4 * c + 3] += vv.w;
                }
            }

            u64 p[10];
            const u64* bp3 = (const u64*)&fw[400];
            #pragma unroll
            for (int j = 0; j < 10; j++) p[j] = bp3[j];
            #pragma unroll
            for (int k = 0; k < 20; k++) {
                u64 xx = pk2(m[k]);
                const ulonglong2* wr = (const ulonglong2*)&fw[k * 20];
                #pragma unroll
                for (int j2 = 0; j2 < 5; j2++) {
                    ulonglong2 wv = wr[j2];
                    p[2 * j2 + 0] = ffma2(xx, wv.x, p[2 * j2 + 0]);
                    p[2 * j2 + 1] = ffma2(xx, wv.y, p[2 * j2 + 1]);
                }
            }
            float pt2[20];
            #pragma unroll
            for (int j = 0; j < 10; j++) {
                float a, c; upk(p[j], a, c);
                pt2[2 * j + 0] = fast_tanh(a);
                pt2[2 * j + 1] = fast_tanh(c);
            }

            u64 qq[6];
            const u64* bp4 = (const u64*)&fw[660];
            #pragma unroll
            for (int j = 0; j < 6; j++) qq[j] = bp4[j];
            #pragma unroll
            for (int k = 0; k < 20; k++) {
                u64 xx = pk2(pt2[k]);
                const ulonglong2* wr = (const ulonglong2*)&fw[420 + k * 12];
                #pragma unroll
                for (int j2 = 0; j2 < 3; j2++) {
                    ulonglong2 wv = wr[j2];
                    qq[2 * j2 + 0] = ffma2(xx, wv.x, qq[2 * j2 + 0]);
                    qq[2 * j2 + 1] = ffma2(xx, wv.y, qq[2 * j2 + 1]);
                }
            }

            float ev = fw[685];
            #pragma unroll
            for (int j = 0; j < 6; j++) {
                float a, c; upk(qq[j], a, c);
                ev += fast_tanh(a) * fw[672 + 2 * j + 0];
                ev += fast_tanh(c) * fw[672 + 2 * j + 1];
            }
            contrib = wt * ev;
        }

        // warp-shuffle reduce + one atomic
        float v = contrib;
        #pragma unroll
        for (int o2 = 16; o2 > 0; o2 >>= 1)
            v += __shfl_down_sync(0xffffffffu, v, o2);
        if (lane == 0) smf[RED_OFF / 4 + warp] = v;
        __syncthreads();
        if (tid == 0) {
            float s = smf[RED_OFF / 4 + 0] + smf[RED_OFF / 4 + 1]
                    + smf[RED_OFF / 4 + 2] + smf[RED_OFF / 4 + 3];
            atomicAdd(&out[bq], SIGMA_C * s);
        }
    }
}

extern "C" void kernel_launch(void* const* d_in, const int* in_sizes, int n_in,
                              void* d_out, int out_size)
{
    const float* feat  = (const float*)d_in[0];
    const float* nbc   = (const float*)d_in[1];
    const float* wts   = (const float*)d_in[2];
    const float* wscal = (const float*)d_in[3];
    const float* w0 = (const float*)d_in[4];
    const float* b0 = (const float*)d_in[5];
    const float* w1 = (const float*)d_in[6];
    const float* b1 = (const float*)d_in[7];
    const float* w2 = (const float*)d_in[8];
    const float* b2 = (const float*)d_in[9];
    const float* w3 = (const float*)d_in[10];
    const float* b3 = (const float*)d_in[11];
    const float* w4 = (const float*)d_in[12];
    const float* b4 = (const float*)d_in[13];
    const float* wf = (const float*)d_in[14];
    const float* bff = (const float*)d_in[15];
    float* out = (float*)d_out;

    const int N = in_sizes[2];
    const int B = out_size;

    cudaFuncSetAttribute(gnn_mma_kernel, cudaFuncAttributeMaxDynamicSharedMemorySize, SMEM_BYTES);

    init_out_kernel<<<1, 32>>>(out, B);
    dim3 grid((N + 63) / 64);
    gnn_mma_kernel<<<grid, 128, SMEM_BYTES>>>(feat, nbc, wts, wscal,
                                              w0, b0, w1, b1, w2, b2,
                                              w3, b3, w4, b4, wf, bff,
                                              out, N, B);
}

// round 10
// speedup vs baseline: 1.1753x; 1.1753x over previous
#include <cuda_runtime.h>
#include <cuda_bf16.h>
#include <cstdint>

typedef unsigned int u32;
typedef unsigned long long u64;

#define SIGMA_C 162.13039087945623f
#define MU_C    117.41975505778706f

// ---- smem byte offsets ----
#define P_OFF     0        /* 448 rows x 20 bf16 (40 B) = 17920; overlaid by W tables at init */
#define W0P_OFF   0        /* 40 x 48 f32 = 7680 */
#define W1P_OFF   7680     /* 24 x 48 f32 = 4608 */
#define W2P_OFF   12288    /* 24 x 32 f32 = 3072 (ends 15360 < 17920) */
#define X0_OFF    17920    /* 64 rows x 112 B bf16 */
#define X1_OFF    25088
#define CS_OFF    32256    /* 448 f32 */
#define BIAS0_OFF 34048    /* 48 f32 */
#define BIAS1_OFF 34240    /* 24 f32 */
#define BIAS2_OFF 34336    /* 24 f32 */
#define FCW_OFF   34432    /* 686 f32 */
#define RED_OFF   37184    /* 4 f32 */
#define SMEM_BYTES 37376

static __device__ __forceinline__ u32 smem_u32(const void* p) {
    u32 a;
    asm("{ .reg .u64 t; cvta.to.shared.u64 t, %1; cvt.u32.u64 %0, t; }" : "=r"(a) : "l"(p));
    return a;
}
static __device__ __forceinline__ float fast_tanh(float x) {
    float y; asm("tanh.approx.f32 %0, %1;" : "=f"(y) : "f"(x)); return y;
}
#define CVT2(res, lo, hi) \
    asm("cvt.rn.bf16x2.f32 %0, %1, %2;" : "=r"(res) : "f"(hi), "f"(lo))
#define TANH2(d, s) \
    asm("tanh.approx.bf16x2 %0, %1;" : "=r"(d) : "r"(s))
#define MULB2(d, a, b) \
    asm("mul.bf16x2 %0, %1, %2;" : "=r"(d) : "r"(a), "r"(b))

static __device__ __forceinline__ void mma16816(float* d, const u32* a, const u32* b) {
    asm volatile("mma.sync.aligned.m16n8k16.row.col.f32.bf16.bf16.f32 "
        "{%0,%1,%2,%3}, {%4,%5,%6,%7}, {%8,%9}, {%0,%1,%2,%3};"
        : "+f"(d[0]), "+f"(d[1]), "+f"(d[2]), "+f"(d[3])
        : "r"(a[0]), "r"(a[1]), "r"(a[2]), "r"(a[3]), "r"(b[0]), "r"(b[1]));
}
static __device__ __forceinline__ void ldm4(u32* r, u32 addr) {
    asm volatile("ldmatrix.sync.aligned.m8n8.x4.shared.b16 {%0,%1,%2,%3}, [%4];"
        : "=r"(r[0]), "=r"(r[1]), "=r"(r[2]), "=r"(r[3]) : "r"(addr));
}
static __device__ __forceinline__ u64 pk2(float x) {
    u64 r; asm("mov.b64 %0, {%1, %1};" : "=l"(r) : "f"(x)); return r;
}
static __device__ __forceinline__ void upk(u64 v, float& a, float& b) {
    asm("mov.b64 {%0, %1}, %2;" : "=f"(a), "=f"(b) : "l"(v));
}
static __device__ __forceinline__ u64 ffma2(u64 a, u64 b, u64 c) {
    u64 d; asm("fma.rn.f32x2 %0, %1, %2, %3;" : "=l"(d) : "l"(a), "l"(b), "l"(c)); return d;
}

__global__ void __launch_bounds__(32) init_out_kernel(float* out, int B) {
    int i = threadIdx.x;
    if (i < B) out[i] = MU_C;
}

__global__ void __launch_bounds__(128, 3) gnn_mma_kernel(
    const float* __restrict__ feat,
    const float* __restrict__ nbc,
    const float* __restrict__ wts,
    const float* __restrict__ wscal,
    const float* __restrict__ w0, const float* __restrict__ b0,
    const float* __restrict__ w1, const float* __restrict__ b1,
    const float* __restrict__ w2, const float* __restrict__ b2,
    const float* __restrict__ w3, const float* __restrict__ b3,
    const float* __restrict__ w4, const float* __restrict__ b4,
    const float* __restrict__ wf, const float* __restrict__ bff,
    float* __restrict__ out, int N, int B)
{
    extern __shared__ char smem[];
    float* smf = (float*)smem;
    const int tid  = threadIdx.x;
    const int warp = tid >> 5;
    const int lane = tid & 31;
    const int n0 = blockIdx.x * 64;
    const int nvalid = (N - n0 < 64) ? (N - n0) : 64;
    const int vrows = nvalid * 7;
    const u32 sb = smem_u32(smem);

    // ---- one-time init ----
    {
        float* w0p = smf + W0P_OFF / 4;
        for (int i = tid; i < 40 * 48; i += 128) { int n = i / 48, k = i % 48; w0p[i] = (k < 40) ? w0[n * 40 + k] : 0.f; }
        float* w1p = smf + W1P_OFF / 4;
        for (int i = tid; i < 24 * 48; i += 128) { int n = i / 48, k = i % 48; w1p[i] = (n < 20 && k < 40) ? w1[n * 40 + k] : 0.f; }
        float* w2p = smf + W2P_OFF / 4;
        for (int i = tid; i < 24 * 32; i += 128) { int n = i / 32, k = i % 32; w2p[i] = (n < 20 && k < 20) ? w2[n * 20 + k] : 0.f; }
        float* bb0s = smf + BIAS0_OFF / 4;
        for (int i = tid; i < 48; i += 128) bb0s[i] = (i < 40) ? b0[i] : 0.f;
        float* bb1s = smf + BIAS1_OFF / 4;
        for (int i = tid; i < 24; i += 128) bb1s[i] = (i < 20) ? b1[i] : 0.f;
        float* bb2s = smf + BIAS2_OFF / 4;
        for (int i = tid; i < 24; i += 128) bb2s[i] = (i < 20) ? b2[i] : 0.f;
        float* fw = smf + FCW_OFF / 4;
        for (int i = tid; i < 400; i += 128) { int j = i / 20, k = i % 20; fw[k * 20 + j] = w3[i]; }
        for (int i = tid; i < 20;  i += 128) fw[400 + i] = b3[i];
        for (int i = tid; i < 240; i += 128) { int k = i / 12, j = i % 12; fw[420 + i] = (j < 10) ? w4[j * 20 + k] : 0.f; }
        for (int i = tid; i < 12;  i += 128) fw[660 + i] = (i < 10) ? b4[i] : 0.f;
        for (int i = tid; i < 12;  i += 128) fw[672 + i] = (i < 10) ? wf[i] : 0.f;
        if (tid == 0) { fw[684] = wscal[0]; fw[685] = bff[0]; }

        if (tid < 64) {
            float cs[7] = {0.f, 0.f, 0.f, 0.f, 0.f, 0.f, 0.f};
            int node = n0 + tid;
            if (node < N) {
                float c0a = nbc[node * 6 + 0], c0b = nbc[node * 6 + 1], c0c = nbc[node * 6 + 2];
                float c1a = nbc[node * 6 + 3], c1b = nbc[node * 6 + 4], c1c = nbc[node * 6 + 5];
                float w_ = wscal[0];
                float nb0 = c0a + c0b + c0c, nb1 = c1a + c1b + c1c;
                float nb0s = (nb0 < 1e-5f) ? 1e-5f : nb0;
                float nb1s = (nb1 < 1e-5f) ? 1e-5f : nb1;
                float h0 = (nb0 > 0.f) ? 1.f : 0.f;
                float h1 = (nb1 > 0.f) ? 1.f : 0.f;
                float inv0 = w_ / nb0s, inv1 = w_ / nb1s;
                cs[0] = 1.f - h0 * w_ - h1 * w_;
                cs[1] = c0a * inv0; cs[2] = c0b * inv0; cs[3] = c0c * inv0;
                cs[4] = c1a * inv1; cs[5] = c1b * inv1; cs[6] = c1c * inv1;
            }
            #pragma unroll
            for (int s = 0; s < 7; s++) smf[CS_OFF / 4 + tid * 7 + s] = cs[s];
        }

        // zero k-pad columns (bytes 80..111) of both X buffers
        for (int i = tid; i < 128; i += 128) {
            int buf = i >> 6, row = i & 63;
            u32* pz = (u32*)(smem + (buf ? X1_OFF : X0_OFF) + row * 112 + 80);
            #pragma unroll
            for (int c = 0; c < 8; c++) pz[c] = 0u;
        }
    }
    __syncthreads();

    // ---- persistent B fragments ----
    const int q = lane & 3;
    const int nn = lane >> 2;
    u32 w0f[15][2], w1f[9][2], w2f[6][2];
    {
        const float* w0p = smf + W0P_OFF / 4;
        #pragma unroll
        for (int f = 0; f < 3; f++)
            #pragma unroll
            for (int j = 0; j < 5; j++) {
                int k0 = f * 16 + 2 * q;
                const float* r = &w0p[(j * 8 + nn) * 48];
                CVT2(w0f[f * 5 + j][0], r[k0 + 0], r[k0 + 1]);
                CVT2(w0f[f * 5 + j][1], r[k0 + 8], r[k0 + 9]);
            }
        const float* w1p = smf + W1P_OFF / 4;
        #pragma unroll
        for (int f = 0; f < 3; f++)
            #pragma unroll
            for (int j = 0; j < 3; j++) {
                int k0 = f * 16 + 2 * q;
                const float* r = &w1p[(j * 8 + nn) * 48];
                CVT2(w1f[f * 3 + j][0], r[k0 + 0], r[k0 + 1]);
                CVT2(w1f[f * 3 + j][1], r[k0 + 8], r[k0 + 9]);
            }
        const float* w2p = smf + W2P_OFF / 4;
        #pragma unroll
        for (int f = 0; f < 2; f++)
            #pragma unroll
            for (int j = 0; j < 3; j++) {
                int k0 = f * 16 + 2 * q;
                const float* r = &w2p[(j * 8 + nn) * 32];
                CVT2(w2f[f * 3 + j][0], r[k0 + 0], r[k0 + 1]);
                CVT2(w2f[f * 3 + j][1], r[k0 + 8], r[k0 + 9]);
            }
    }

    // ---- bias registers for accumulator init ----
    float bl0[5], bh0[5], bl1[3], bh1[3], bl2[3], bh2[3];
    {
        const float* bb0 = smf + BIAS0_OFF / 4;
        const float* bb1 = smf + BIAS1_OFF / 4;
        const float* bb2 = smf + BIAS2_OFF / 4;
        #pragma unroll
        for (int j = 0; j < 5; j++) { bl0[j] = bb0[j * 8 + 2 * q]; bh0[j] = bb0[j * 8 + 2 * q + 1]; }
        #pragma unroll
        for (int j = 0; j < 3; j++) { bl1[j] = bb1[j * 8 + 2 * q]; bh1[j] = bb1[j * 8 + 2 * q + 1]; }
        #pragma unroll
        for (int j = 0; j < 3; j++) { bl2[j] = bb2[j * 8 + 2 * q]; bh2[j] = bb2[j * 8 + 2 * q + 1]; }
    }

    const float* csa = smf + CS_OFF / 4;
    const float* fw  = smf + FCW_OFF / 4;

    int srow[5], soff[5], goff[5];
    #pragma unroll
    for (int it = 0; it < 5; it++) {
        int i = it * 128 + tid;
        int row = i / 10, qq = i % 10;
        srow[it] = row;
        soff[it] = row * 112 + qq * 8;
        goff[it] = row * 10 + qq;
    }

    const int lg = lane >> 3, lr = lane & 7;
    const int arow = warp * 16 + (lg & 1) * 8 + lr;
    const int acolb = (lg >> 1) * 8;
    const int prow = warp * 16 + (lane >> 2);

    const float wt = (tid < nvalid) ? wts[n0 + tid] : 0.f;

    float4 xv[5];

    #pragma unroll 1
    for (int bq = 0; bq < B; bq++) {
        const float4* fbB = (const float4*)feat + ((size_t)bq * N + n0) * 70;

        if (bq == 0) {
            #pragma unroll
            for (int it = 0; it < 5; it++)
                if (srow[it] < vrows) xv[it] = fbB[goff[it]];
        }

        #pragma unroll 1
        for (int t = 0; t < 7; t++) {
            const u32 xbase = sb + ((t & 1) ? X1_OFF : X0_OFF);

            // convert + STS current tile
            #pragma unroll
            for (int it = 0; it < 5; it++) {
                u32 p0, p1;
                CVT2(p0, xv[it].x, xv[it].y);
                CVT2(p1, xv[it].z, xv[it].w);
                asm volatile("st.shared.v2.b32 [%0], {%1, %2};"
                             :: "r"(xbase + (u32)soff[it]), "r"(p0), "r"(p1) : "memory");
            }
            // prefetch next tile (or next batch tile 0) BEFORE the barrier
            if (t < 6) {
                #pragma unroll
                for (int it = 0; it < 5; it++)
                    if ((t + 1) * 64 + srow[it] < vrows) xv[it] = fbB[(t + 1) * 640 + goff[it]];
            } else if (bq + 1 < B) {
                const float4* fbN = (const float4*)feat + ((size_t)(bq + 1) * N + n0) * 70;
                #pragma unroll
                for (int it = 0; it < 5; it++)
                    if (srow[it] < vrows) xv[it] = fbN[goff[it]];
            }
            __syncthreads();

            // ---- fc0 chain for this warp's 16 rows ----
            u32 a0f[3][4];
            #pragma unroll
            for (int f = 0; f < 3; f++)
                ldm4(a0f[f], xbase + (u32)(arow * 112 + (f * 16 + acolb) * 2));

            // L0 (bias in accumulator)
            float d[5][4];
            #pragma unroll
            for (int j = 0; j < 5; j++) { d[j][0] = bl0[j]; d[j][1] = bh0[j]; d[j][2] = bl0[j]; d[j][3] = bh0[j]; }
            #pragma unroll
            for (int f = 0; f < 3; f++)
                #pragma unroll
                for (int j = 0; j < 5; j++)
                    mma16816(d[j], a0f[f], w0f[f * 5 + j]);

            // epi1: pack -> tanh.bf16x2
            u32 a1f[3][4];
            #pragma unroll
            for (int j = 0; j < 5; j++) {
                u32 plo, phi;
                CVT2(plo, d[j][0], d[j][1]); TANH2(plo, plo);
                CVT2(phi, d[j][2], d[j][3]); TANH2(phi, phi);
                a1f[j >> 1][(j & 1) ? 2 : 0] = plo;
                a1f[j >> 1][(j & 1) ? 3 : 1] = phi;
            }
            a1f[2][2] = 0u; a1f[2][3] = 0u;

            // L1
            float e[3][4];
            #pragma unroll
            for (int j = 0; j < 3; j++) { e[j][0] = bl1[j]; e[j][1] = bh1[j]; e[j][2] = bl1[j]; e[j][3] = bh1[j]; }
            #pragma unroll
            for (int f = 0; f < 3; f++)
                #pragma unroll
                for (int j = 0; j < 3; j++)
                    mma16816(e[j], a1f[f], w1f[f * 3 + j]);

            // epi2 (pads are tanh(0)=0 naturally)
            u32 a2f[2][4];
            #pragma unroll
            for (int j = 0; j < 3; j++) {
                u32 plo, phi;
                CVT2(plo, e[j][0], e[j][1]); TANH2(plo, plo);
                CVT2(phi, e[j][2], e[j][3]); TANH2(phi, phi);
                a2f[j >> 1][(j & 1) ? 2 : 0] = plo;
                a2f[j >> 1][(j & 1) ? 3 : 1] = phi;
            }
            a2f[1][2] = 0u; a2f[1][3] = 0u;

            // L2
            float o[3][4];
            #pragma unroll
            for (int j = 0; j < 3; j++) { o[j][0] = bl2[j]; o[j][1] = bh2[j]; o[j][2] = bl2[j]; o[j][3] = bh2[j]; }
            #pragma unroll
            for (int f = 0; f < 2; f++)
                #pragma unroll
                for (int j = 0; j < 3; j++)
                    mma16816(o[j], a2f[f], w2f[f * 3 + j]);

            // epi3: tanh.bf16x2 * cs -> bf16 P
            {
                int r0 = t * 64 + prow;
                int r1 = r0 + 8;
                float cs0 = csa[r0], cs1 = csa[r1];
                u32 cb0, cb1;
                CVT2(cb0, cs0, cs0);
                CVT2(cb1, cs1, cs1);
                #pragma unroll
                for (int j = 0; j < 3; j++) {
                    int c0 = j * 8 + 2 * q;
                    if (c0 < 20) {
                        u32 plo, phi;
                        CVT2(plo, o[j][0], o[j][1]); TANH2(plo, plo); MULB2(plo, plo, cb0);
                        CVT2(phi, o[j][2], o[j][3]); TANH2(phi, phi); MULB2(phi, phi, cb1);
                        asm volatile("st.shared.b32 [%0], %1;"
                                     :: "r"(sb + P_OFF + (u32)(r0 * 40 + c0 * 2)), "r"(plo) : "memory");
                        asm volatile("st.shared.b32 [%0], %1;"
                                     :: "r"(sb + P_OFF + (u32)(r1 * 40 + c0 * 2)), "r"(phi) : "memory");
                    }
                }
            }
        }
        __syncthreads();   // P complete

        // ---- tail: gather P (bf16), fc1, head ----
        float contrib = 0.f;
        if (tid < nvalid) {
            float m[20];
            #pragma unroll
            for (int d2 = 0; d2 < 20; d2++) m[d2] = 0.f;
            #pragma unroll
            for (int s = 0; s < 7; s++) {
                const u32* pr = (const u32*)(smem + P_OFF + (u32)((tid * 7 + s) * 40));
                #pragma unroll
                for (int c = 0; c < 10; c++) {
                    u32 v = pr[c];
                    m[2 * c + 0] += __uint_as_float(v << 16);
                    m[2 * c + 1] += __uint_as_float(v & 0xffff0000u);
                }
            }

            u64 p[10];
            const u64* bp3 = (const u64*)&fw[400];
            #pragma unroll
            for (int j = 0; j < 10; j++) p[j] = bp3[j];
            #pragma unroll
            for (int k = 0; k < 20; k++) {
                u64 xx = pk2(m[k]);
                const ulonglong2* wr = (const ulonglong2*)&fw[k * 20];
                #pragma unroll
                for (int j2 = 0; j2 < 5; j2++) {
                    ulonglong2 wv = wr[j2];
                    p[2 * j2 + 0] = ffma2(xx, wv.x, p[2 * j2 + 0]);
                    p[2 * j2 + 1] = ffma2(xx, wv.y, p[2 * j2 + 1]);
                }
            }
            float pt2[20];
            #pragma unroll
            for (int j = 0; j < 10; j++) {
                float a, c; upk(p[j], a, c);
                pt2[2 * j + 0] = fast_tanh(a);
                pt2[2 * j + 1] = fast_tanh(c);
            }

            u64 qq[6];
            const u64* bp4 = (const u64*)&fw[660];
            #pragma unroll
            for (int j = 0; j < 6; j++) qq[j] = bp4[j];
            #pragma unroll
            for (int k = 0; k < 20; k++) {
                u64 xx = pk2(pt2[k]);
                const ulonglong2* wr = (const ulonglong2*)&fw[420 + k * 12];
                #pragma unroll
                for (int j2 = 0; j2 < 3; j2++) {
                    ulonglong2 wv = wr[j2];
                    qq[2 * j2 + 0] = ffma2(xx, wv.x, qq[2 * j2 + 0]);
                    qq[2 * j2 + 1] = ffma2(xx, wv.y, qq[2 * j2 + 1]);
                }
            }

            float ev = fw[685];
            #pragma unroll
            for (int j = 0; j < 6; j++) {
                float a, c; upk(qq[j], a, c);
                ev += fast_tanh(a) * fw[672 + 2 * j + 0];
                ev += fast_tanh(c) * fw[672 + 2 * j + 1];
            }
            contrib = wt * ev;
        }

        // warp-shuffle reduce + one atomic
        float v = contrib;
        #pragma unroll
        for (int o2 = 16; o2 > 0; o2 >>= 1)
            v += __shfl_down_sync(0xffffffffu, v, o2);
        if (lane == 0) smf[RED_OFF / 4 + warp] = v;
        __syncthreads();
        if (tid == 0) {
            float s = smf[RED_OFF / 4 + 0] + smf[RED_OFF / 4 + 1]
                    + smf[RED_OFF / 4 + 2] + smf[RED_OFF / 4 + 3];
            atomicAdd(&out[bq], SIGMA_C * s);
        }
    }
}

extern "C" void kernel_launch(void* const* d_in, const int* in_sizes, int n_in,
                              void* d_out, int out_size)
{
    const float* feat  = (const float*)d_in[0];
    const float* nbc   = (const float*)d_in[1];
    const float* wts   = (const float*)d_in[2];
    const float* wscal = (const float*)d_in[3];
    const float* w0 = (const float*)d_in[4];
    const float* b0 = (const float*)d_in[5];
    const float* w1 = (const float*)d_in[6];
    const float* b1 = (const float*)d_in[7];
    const float* w2 = (const float*)d_in[8];
    const float* b2 = (const float*)d_in[9];
    const float* w3 = (const float*)d_in[10];
    const float* b3 = (const float*)d_in[11];
    const float* w4 = (const float*)d_in[12];
    const float* b4 = (const float*)d_in[13];
    const float* wf = (const float*)d_in[14];
    const float* bff = (const float*)d_in[15];
    float* out = (float*)d_out;

    const int N = in_sizes[2];
    const int B = out_size;

    cudaFuncSetAttribute(gnn_mma_kernel, cudaFuncAttributeMaxDynamicSharedMemorySize, SMEM_BYTES);

    init_out_kernel<<<1, 32>>>(out, B);
    dim3 grid((N + 63) / 64);
    gnn_mma_kernel<<<grid, 128, SMEM_BYTES>>>(feat, nbc, wts, wscal,
                                              w0, b0, w1, b1, w2, b2,
                                              w3, b3, w4, b4, wf, bff,
                                              out, N, B);
}

// round 11
// speedup vs baseline: 1.3689x; 1.1647x over previous
#include <cuda_runtime.h>
#include <cuda_bf16.h>
#include <cstdint>

typedef unsigned int u32;
typedef unsigned long long u64;

#define SIGMA_C 162.13039087945623f
#define MU_C    117.41975505778706f

// ---- smem byte offsets ----
#define M_OFF     0        /* 64 x 20 f32 = 5120 B; overlaid by weight tables at init */
#define W0P_OFF   0        /* 40 x 48 f32 */
#define W1P_OFF   7680     /* 24 x 48 f32 */
#define W2P_OFF   12288    /* 24 x 32 f32, ends 15360 */
#define X_OFF     15360    /* 2 buffers x (4 warps x 16 rows x 112 B) = 14336 */
#define CS_OFF    29696    /* 448 f32 */
#define BIAS0_OFF 31488    /* 48 f32 */
#define BIAS1_OFF 31680    /* 24 f32 */
#define BIAS2_OFF 31776    /* 24 f32 */
#define FCW_OFF   31872    /* 686 f32 */
#define RED_OFF   34616    /* 4 f32 */
#define SMEM_BYTES 34688

static __device__ __forceinline__ u32 smem_u32(const void* p) {
    u32 a;
    asm("{ .reg .u64 t; cvta.to.shared.u64 t, %1; cvt.u32.u64 %0, t; }" : "=r"(a) : "l"(p));
    return a;
}
static __device__ __forceinline__ float fast_tanh(float x) {
    float y; asm("tanh.approx.f32 %0, %1;" : "=f"(y) : "f"(x)); return y;
}
#define CVT2(res, lo, hi) \
    asm("cvt.rn.bf16x2.f32 %0, %1, %2;" : "=r"(res) : "f"(hi), "f"(lo))
#define TANH2(d, s) \
    asm("tanh.approx.bf16x2 %0, %1;" : "=r"(d) : "r"(s))

static __device__ __forceinline__ void mma16816(float* d, const u32* a, const u32* b) {
    asm volatile("mma.sync.aligned.m16n8k16.row.col.f32.bf16.bf16.f32 "
        "{%0,%1,%2,%3}, {%4,%5,%6,%7}, {%8,%9}, {%0,%1,%2,%3};"
        : "+f"(d[0]), "+f"(d[1]), "+f"(d[2]), "+f"(d[3])
        : "r"(a[0]), "r"(a[1]), "r"(a[2]), "r"(a[3]), "r"(b[0]), "r"(b[1]));
}
static __device__ __forceinline__ void ldm4(u32* r, u32 addr) {
    asm volatile("ldmatrix.sync.aligned.m8n8.x4.shared.b16 {%0,%1,%2,%3}, [%4];"
        : "=r"(r[0]), "=r"(r[1]), "=r"(r[2]), "=r"(r[3]) : "r"(addr));
}
static __device__ __forceinline__ u64 pk2(float x) {
    u64 r; asm("mov.b64 %0, {%1, %1};" : "=l"(r) : "f"(x)); return r;
}
static __device__ __forceinline__ void upk(u64 v, float& a, float& b) {
    asm("mov.b64 {%0, %1}, %2;" : "=f"(a), "=f"(b) : "l"(v));
}
static __device__ __forceinline__ u64 ffma2(u64 a, u64 b, u64 c) {
    u64 d; asm("fma.rn.f32x2 %0, %1, %2, %3;" : "=l"(d) : "l"(a), "l"(b), "l"(c)); return d;
}

__global__ void __launch_bounds__(32) init_out_kernel(float* out, int B) {
    int i = threadIdx.x;
    if (i < B) out[i] = MU_C;
}

__global__ void __launch_bounds__(128, 3) gnn_mma_kernel(
    const float* __restrict__ feat,
    const float* __restrict__ nbc,
    const float* __restrict__ wts,
    const float* __restrict__ wscal,
    const float* __restrict__ w0, const float* __restrict__ b0,
    const float* __restrict__ w1, const float* __restrict__ b1,
    const float* __restrict__ w2, const float* __restrict__ b2,
    const float* __restrict__ w3, const float* __restrict__ b3,
    const float* __restrict__ w4, const float* __restrict__ b4,
    const float* __restrict__ wf, const float* __restrict__ bff,
    float* __restrict__ out, int N, int B)
{
    extern __shared__ char smem[];
    float* smf = (float*)smem;
    const int tid  = threadIdx.x;
    const int warp = tid >> 5;
    const int lane = tid & 31;
    const int n0 = blockIdx.x * 64;
    const int nvalid = (N - n0 < 64) ? (N - n0) : 64;
    const int vq = nvalid * 70;     // valid quads per tile
    const u32 sb = smem_u32(smem);

    // ---- one-time init ----
    {
        float* w0p = smf + W0P_OFF / 4;
        for (int i = tid; i < 40 * 48; i += 128) { int n = i / 48, k = i % 48; w0p[i] = (k < 40) ? w0[n * 40 + k] : 0.f; }
        float* w1p = smf + W1P_OFF / 4;
        for (int i = tid; i < 24 * 48; i += 128) { int n = i / 48, k = i % 48; w1p[i] = (n < 20 && k < 40) ? w1[n * 40 + k] : 0.f; }
        float* w2p = smf + W2P_OFF / 4;
        for (int i = tid; i < 24 * 32; i += 128) { int n = i / 32, k = i % 32; w2p[i] = (n < 20 && k < 20) ? w2[n * 20 + k] : 0.f; }
        float* bb0s = smf + BIAS0_OFF / 4;
        for (int i = tid; i < 48; i += 128) bb0s[i] = (i < 40) ? b0[i] : 0.f;
        float* bb1s = smf + BIAS1_OFF / 4;
        for (int i = tid; i < 24; i += 128) bb1s[i] = (i < 20) ? b1[i] : 0.f;
        float* bb2s = smf + BIAS2_OFF / 4;
        for (int i = tid; i < 24; i += 128) bb2s[i] = (i < 20) ? b2[i] : 0.f;
        float* fw = smf + FCW_OFF / 4;
        for (int i = tid; i < 400; i += 128) { int j = i / 20, k = i % 20; fw[k * 20 + j] = w3[i]; }
        for (int i = tid; i < 20;  i += 128) fw[400 + i] = b3[i];
        for (int i = tid; i < 240; i += 128) { int k = i / 12, j = i % 12; fw[420 + i] = (j < 10) ? w4[j * 20 + k] : 0.f; }
        for (int i = tid; i < 12;  i += 128) fw[660 + i] = (i < 10) ? b4[i] : 0.f;
        for (int i = tid; i < 12;  i += 128) fw[672 + i] = (i < 10) ? wf[i] : 0.f;
        if (tid == 0) { fw[684] = wscal[0]; fw[685] = bff[0]; }

        if (tid < 64) {
            float cs[7] = {0.f, 0.f, 0.f, 0.f, 0.f, 0.f, 0.f};
            int node = n0 + tid;
            if (node < N) {
                float c0a = nbc[node * 6 + 0], c0b = nbc[node * 6 + 1], c0c = nbc[node * 6 + 2];
                float c1a = nbc[node * 6 + 3], c1b = nbc[node * 6 + 4], c1c = nbc[node * 6 + 5];
                float w_ = wscal[0];
                float nb0 = c0a + c0b + c0c, nb1 = c1a + c1b + c1c;
                float nb0s = (nb0 < 1e-5f) ? 1e-5f : nb0;
                float nb1s = (nb1 < 1e-5f) ? 1e-5f : nb1;
                float h0 = (nb0 > 0.f) ? 1.f : 0.f;
                float h1 = (nb1 > 0.f) ? 1.f : 0.f;
                float inv0 = w_ / nb0s, inv1 = w_ / nb1s;
                cs[0] = 1.f - h0 * w_ - h1 * w_;
                cs[1] = c0a * inv0; cs[2] = c0b * inv0; cs[3] = c0c * inv0;
                cs[4] = c1a * inv1; cs[5] = c1b * inv1; cs[6] = c1c * inv1;
            }
            #pragma unroll
            for (int s = 0; s < 7; s++) smf[CS_OFF / 4 + tid * 7 + s] = cs[s];
        }

        // zero k-pad columns (bytes 80..111) of all 128 slab rows (2 buffers x 64 rows)
        for (int i = tid; i < 128; i += 128) {
            int buf = i >> 6, r = i & 63;
            u32* pz = (u32*)(smem + X_OFF + buf * 7168 + r * 112 + 80);
            #pragma unroll
            for (int c = 0; c < 8; c++) pz[c] = 0u;
        }
    }
    __syncthreads();

    // ---- persistent B fragments ----
    const int q = lane & 3;
    const int nn = lane >> 2;
    u32 w0f[15][2], w1f[9][2], w2f[6][2];
    {
        const float* w0p = smf + W0P_OFF / 4;
        #pragma unroll
        for (int f = 0; f < 3; f++)
            #pragma unroll
            for (int j = 0; j < 5; j++) {
                int k0 = f * 16 + 2 * q;
                const float* r = &w0p[(j * 8 + nn) * 48];
                CVT2(w0f[f * 5 + j][0], r[k0 + 0], r[k0 + 1]);
                CVT2(w0f[f * 5 + j][1], r[k0 + 8], r[k0 + 9]);
            }
        const float* w1p = smf + W1P_OFF / 4;
        #pragma unroll
        for (int f = 0; f < 3; f++)
            #pragma unroll
            for (int j = 0; j < 3; j++) {
                int k0 = f * 16 + 2 * q;
                const float* r = &w1p[(j * 8 + nn) * 48];
                CVT2(w1f[f * 3 + j][0], r[k0 + 0], r[k0 + 1]);
                CVT2(w1f[f * 3 + j][1], r[k0 + 8], r[k0 + 9]);
            }
        const float* w2p = smf + W2P_OFF / 4;
        #pragma unroll
        for (int f = 0; f < 2; f++)
            #pragma unroll
            for (int j = 0; j < 3; j++) {
                int k0 = f * 16 + 2 * q;
                const float* r = &w2p[(j * 8 + nn) * 32];
                CVT2(w2f[f * 3 + j][0], r[k0 + 0], r[k0 + 1]);
                CVT2(w2f[f * 3 + j][1], r[k0 + 8], r[k0 + 9]);
            }
    }
    // weight tables in smem no longer needed; M buffer overlays them.
    __syncthreads();

    // ---- bias registers for L1/L2 accumulator init (L0 bias stays in smem) ----
    float bl1[3], bh1[3], bl2[3], bh2[3];
    {
        const float* bb1 = smf + BIAS1_OFF / 4;
        const float* bb2 = smf + BIAS2_OFF / 4;
        #pragma unroll
        for (int j = 0; j < 3; j++) { bl1[j] = bb1[j * 8 + 2 * q]; bh1[j] = bb1[j * 8 + 2 * q + 1]; }
        #pragma unroll
        for (int j = 0; j < 3; j++) { bl2[j] = bb2[j * 8 + 2 * q]; bh2[j] = bb2[j * 8 + 2 * q + 1]; }
    }

    const float* csa = smf + CS_OFF / 4;
    const float* fw  = smf + FCW_OFF / 4;
    const float* bb0 = smf + BIAS0_OFF / 4;

    // per-lane staging offsets (warp stages its OWN 16 rows: 160 quads / 32 lanes = 5)
    int gq[5], sof[5];
    #pragma unroll
    for (int i = 0; i < 5; i++) {
        int lq = lane + 32 * i;               // 0..159 within warp slab
        gq[i]  = warp * 160 + lq;             // quad index within tile
        sof[i] = warp * 1792 + (lq / 10) * 112 + (lq % 10) * 8;
    }

    // ldmatrix lane addressing (within own warp slab)
    const int lg = lane >> 3, lr = lane & 7;
    const int aoff = warp * 1792 + ((lg & 1) * 8 + lr) * 112;  // row byte offset
    const int acolb = (lg >> 1) * 8;
    const int prow = warp * 16 + nn;           // node-local row this thread owns (and +8)

    const float wt = (tid < nvalid) ? wts[n0 + tid] : 0.f;

    float4 xv[5] = {};

    #pragma unroll 1
    for (int bq = 0; bq < B; bq++) {
        const float4* fbB = (const float4*)feat + ((size_t)bq * N + n0) * 70;

        if (bq == 0) {
            #pragma unroll
            for (int i = 0; i < 5; i++)
                if (gq[i] < vq) xv[i] = fbB[gq[i]];
        }

        // message accumulators (f32 fragments, node rows prow / prow+8)
        float m0[3][4];
        #pragma unroll
        for (int j = 0; j < 3; j++) { m0[j][0] = 0.f; m0[j][1] = 0.f; m0[j][2] = 0.f; m0[j][3] = 0.f; }

        #pragma unroll 1
        for (int t = 0; t < 7; t++) {
            const u32 xslab = sb + X_OFF + (t & 1) * 7168;

            // convert + STS own rows
            #pragma unroll
            for (int i = 0; i < 5; i++) {
                u32 p0, p1;
                CVT2(p0, xv[i].x, xv[i].y);
                CVT2(p1, xv[i].z, xv[i].w);
                asm volatile("st.shared.v2.b32 [%0], {%1, %2};"
                             :: "r"(xslab + (u32)sof[i]), "r"(p0), "r"(p1) : "memory");
            }
            // prefetch next tile / next batch tile 0
            if (t < 6) {
                #pragma unroll
                for (int i = 0; i < 5; i++)
                    if ((t + 1) * 640 + gq[i] < vq) xv[i] = fbB[(t + 1) * 640 + gq[i]];
            } else if (bq + 1 < B) {
                const float4* fbN = (const float4*)feat + ((size_t)(bq + 1) * N + n0) * 70;
                #pragma unroll
                for (int i = 0; i < 5; i++)
                    if (gq[i] < vq) xv[i] = fbN[gq[i]];
            }
            __syncwarp();

            // ---- fc0 chain for this warp's 16 rows ----
            u32 a0f[3][4];
            #pragma unroll
            for (int f = 0; f < 3; f++)
                ldm4(a0f[f], xslab + (u32)(aoff + (f * 16 + acolb) * 2));

            // L0 (bias from smem)
            float d[5][4];
            #pragma unroll
            for (int j = 0; j < 5; j++) {
                float2 bv = *(const float2*)&bb0[j * 8 + 2 * q];
                d[j][0] = bv.x; d[j][1] = bv.y; d[j][2] = bv.x; d[j][3] = bv.y;
            }
            #pragma unroll
            for (int f = 0; f < 3; f++)
                #pragma unroll
                for (int j = 0; j < 5; j++)
                    mma16816(d[j], a0f[f], w0f[f * 5 + j]);

            // epi1
            u32 a1f[3][4];
            #pragma unroll
            for (int j = 0; j < 5; j++) {
                u32 plo, phi;
                CVT2(plo, d[j][0], d[j][1]); TANH2(plo, plo);
                CVT2(phi, d[j][2], d[j][3]); TANH2(phi, phi);
                a1f[j >> 1][(j & 1) ? 2 : 0] = plo;
                a1f[j >> 1][(j & 1) ? 3 : 1] = phi;
            }
            a1f[2][2] = 0u; a1f[2][3] = 0u;

            // L1
            float e[3][4];
            #pragma unroll
            for (int j = 0; j < 3; j++) { e[j][0] = bl1[j]; e[j][1] = bh1[j]; e[j][2] = bl1[j]; e[j][3] = bh1[j]; }
            #pragma unroll
            for (int f = 0; f < 3; f++)
                #pragma unroll
                for (int j = 0; j < 3; j++)
                    mma16816(e[j], a1f[f], w1f[f * 3 + j]);

            // epi2
            u32 a2f[2][4];
            #pragma unroll
            for (int j = 0; j < 3; j++) {
                u32 plo, phi;
                CVT2(plo, e[j][0], e[j][1]); TANH2(plo, plo);
                CVT2(phi, e[j][2], e[j][3]); TANH2(phi, phi);
                a2f[j >> 1][(j & 1) ? 2 : 0] = plo;
                a2f[j >> 1][(j & 1) ? 3 : 1] = phi;
            }
            a2f[1][2] = 0u; a2f[1][3] = 0u;

            // L2
            float o[3][4];
            #pragma unroll
            for (int j = 0; j < 3; j++) { o[j][0] = bl2[j]; o[j][1] = bh2[j]; o[j][2] = bl2[j]; o[j][3] = bh2[j]; }
            #pragma unroll
            for (int f = 0; f < 2; f++)
                #pragma unroll
                for (int j = 0; j < 3; j++)
                    mma16816(o[j], a2f[f], w2f[f * 3 + j]);

            // epi3: accumulate cs * tanh into register message fragments
            {
                int g0 = t * 64 + prow;
                float cs0 = csa[g0], cs1 = csa[g0 + 8];
                #pragma unroll
                for (int j = 0; j < 3; j++) {
                    m0[j][0] += cs0 * fast_tanh(o[j][0]);
                    m0[j][1] += cs0 * fast_tanh(o[j][1]);
                    m0[j][2] += cs1 * fast_tanh(o[j][2]);
                    m0[j][3] += cs1 * fast_tanh(o[j][3]);
                }
            }
        }

        // ---- write message fragments to M (64 x 20 f32) ----
        #pragma unroll
        for (int j = 0; j < 3; j++) {
            int c0 = j * 8 + 2 * q;
            if (c0 < 20) {
                asm volatile("st.shared.v2.b32 [%0], {%1, %2};"
                             :: "r"(sb + M_OFF + (u32)(prow * 80 + c0 * 4)),
                                "r"(__float_as_uint(m0[j][0])), "r"(__float_as_uint(m0[j][1])) : "memory");
                asm volatile("st.shared.v2.b32 [%0], {%1, %2};"
                             :: "r"(sb + M_OFF + (u32)((prow + 8) * 80 + c0 * 4)),
                                "r"(__float_as_uint(m0[j][2])), "r"(__float_as_uint(m0[j][3])) : "memory");
            }
        }
        __syncthreads();   // M complete

        // ---- tail: fc1 + head (threads 0..nvalid) ----
        float contrib = 0.f;
        if (tid < nvalid) {
            float m[20];
            {
                const float4* pr = (const float4*)(smem + M_OFF + (u32)(tid * 80));
                #pragma unroll
                for (int c = 0; c < 5; c++) {
                    float4 vv = pr[c];
                    m[4 * c + 0] = vv.x; m[4 * c + 1] = vv.y;
                    m[4 * c + 2] = vv.z; m[4 * c + 3] = vv.w;
                }
            }

            u64 p[10];
            const u64* bp3 = (const u64*)&fw[400];
            #pragma unroll
            for (int j = 0; j < 10; j++) p[j] = bp3[j];
            #pragma unroll
            for (int k = 0; k < 20; k++) {
                u64 xx = pk2(m[k]);
                const ulonglong2* wr = (const ulonglong2*)&fw[k * 20];
                #pragma unroll
                for (int j2 = 0; j2 < 5; j2++) {
                    ulonglong2 wv = wr[j2];
                    p[2 * j2 + 0] = ffma2(xx, wv.x, p[2 * j2 + 0]);
                    p[2 * j2 + 1] = ffma2(xx, wv.y, p[2 * j2 + 1]);
                }
            }
            float pt2[20];
            #pragma unroll
            for (int j = 0; j < 10; j++) {
                float a, c; upk(p[j], a, c);
                pt2[2 * j + 0] = fast_tanh(a);
                pt2[2 * j + 1] = fast_tanh(c);
            }

            u64 qq[6];
            const u64* bp4 = (const u64*)&fw[660];
            #pragma unroll
            for (int j = 0; j < 6; j++) qq[j] = bp4[j];
            #pragma unroll
            for (int k = 0; k < 20; k++) {
                u64 xx = pk2(pt2[k]);
                const ulonglong2* wr = (const ulonglong2*)&fw[420 + k * 12];
                #pragma unroll
                for (int j2 = 0; j2 < 3; j2++) {
                    ulonglong2 wv = wr[j2];
                    qq[2 * j2 + 0] = ffma2(xx, wv.x, qq[2 * j2 + 0]);
                    qq[2 * j2 + 1] = ffma2(xx, wv.y, qq[2 * j2 + 1]);
                }
            }

            float ev = fw[685];
            #pragma unroll
            for (int j = 0; j < 6; j++) {
                float a, c; upk(qq[j], a, c);
                ev += fast_tanh(a) * fw[672 + 2 * j + 0];
                ev += fast_tanh(c) * fw[672 + 2 * j + 1];
            }
            contrib = wt * ev;
        }

        // warp-shuffle reduce + one atomic
        float v = contrib;
        #pragma unroll
        for (int o2 = 16; o2 > 0; o2 >>= 1)
            v += __shfl_down_sync(0xffffffffu, v, o2);
        if (lane == 0) smf[RED_OFF / 4 + warp] = v;
        __syncthreads();
        if (tid == 0) {
            float s = smf[RED_OFF / 4 + 0] + smf[RED_OFF / 4 + 1]
                    + smf[RED_OFF / 4 + 2] + smf[RED_OFF / 4 + 3];
            atomicAdd(&out[bq], SIGMA_C * s);
        }
    }
}

extern "C" void kernel_launch(void* const* d_in, const int* in_sizes, int n_in,
                              void* d_out, int out_size)
{
    const float* feat  = (const float*)d_in[0];
    const float* nbc   = (const float*)d_in[1];
    const float* wts   = (const float*)d_in[2];
    const float* wscal = (const float*)d_in[3];
    const float* w0 = (const float*)d_in[4];
    const float* b0 = (const float*)d_in[5];
    const float* w1 = (const float*)d_in[6];
    const float* b1 = (const float*)d_in[7];
    const float* w2 = (const float*)d_in[8];
    const float* b2 = (const float*)d_in[9];
    const float* w3 = (const float*)d_in[10];
    const float* b3 = (const float*)d_in[11];
    const float* w4 = (const float*)d_in[12];
    const float* b4 = (const float*)d_in[13];
    const float* wf = (const float*)d_in[14];
    const float* bff = (const float*)d_in[15];
    float* out = (float*)d_out;

    const int N = in_sizes[2];
    const int B = out_size;

    cudaFuncSetAttribute(gnn_mma_kernel, cudaFuncAttributeMaxDynamicSharedMemorySize, SMEM_BYTES);

    init_out_kernel<<<1, 32>>>(out, B);
    dim3 grid((N + 63) / 64);
    gnn_mma_kernel<<<grid, 128, SMEM_BYTES>>>(feat, nbc, wts, wscal,
                                              w0, b0, w1, b1, w2, b2,
                                              w3, b3, w4, b4, wf, bff,
                                              out, N, B);
}